// round 2
// baseline (speedup 1.0000x reference)
#include <cuda_runtime.h>
#include <math.h>

#define NFEAT 64
#define NNODES 50000
#define NEDGES 800000
#define TS 67              // staging stride (gcd(67-64? no: 67 mod 32 = 3, coprime with 32) -> conflict-free)

// Scratch: aggregated edge features per node (scatter target). 12.8 MB.
__device__ float g_agg[NNODES * NFEAT];

__device__ __forceinline__ float tshrink(float x) { return x - tanhf(x); }

// acc[0..63] += x * w[0..63], weights from SHARED memory (broadcast across warp)
__device__ __forceinline__ void fma_dual_sh(float x, const float* wE, const float* wA,
                                            float* u, float* v) {
    const float4* e4 = (const float4*)wE;
    const float4* a4 = (const float4*)wA;
#pragma unroll
    for (int j = 0; j < 16; j++) {
        float4 we = e4[j];
        u[4*j+0] += x * we.x; u[4*j+1] += x * we.y;
        u[4*j+2] += x * we.z; u[4*j+3] += x * we.w;
        float4 wa = a4[j];
        v[4*j+0] += x * wa.x; v[4*j+1] += x * wa.y;
        v[4*j+2] += x * wa.z; v[4*j+3] += x * wa.w;
    }
}

// acc[0..63] += x * w[0..63], weights from GLOBAL (uniform address -> L1 broadcast)
__device__ __forceinline__ void fma_one_g(float x, const float* __restrict__ w, float* acc) {
    const float4* w4 = (const float4*)w;
#pragma unroll
    for (int j = 0; j < 16; j++) {
        float4 t = __ldg(&w4[j]);
        acc[4*j+0] += x * t.x; acc[4*j+1] += x * t.y;
        acc[4*j+2] += x * t.z; acc[4*j+3] += x * t.w;
    }
}

__device__ __forceinline__ void init_from_bias(const float* __restrict__ b, float* acc) {
    const float4* b4 = (const float4*)b;
#pragma unroll
    for (int j = 0; j < 16; j++) {
        float4 t = __ldg(&b4[j]);
        acc[4*j+0] = t.x; acc[4*j+1] = t.y; acc[4*j+2] = t.z; acc[4*j+3] = t.w;
    }
}

// ---------------------------------------------------------------------------
// Init: zero agg buffer, seed coord_out = coord
// ---------------------------------------------------------------------------
__global__ void init_kernel(const float* __restrict__ coord, float* __restrict__ coord_out,
                            int n) {
    int i = blockIdx.x * blockDim.x + threadIdx.x;
    if (i < n * NFEAT) g_agg[i] = 0.0f;
    if (i < n * 3) coord_out[i] = coord[i];
}

// ---------------------------------------------------------------------------
// Edge kernel: one thread per edge.
//   Pass 1: fused edge-MLP-L1 + attention-L1 over gathered [src|tgt|radial]
//   Then: attention scalar, edge-MLP-L2, gate, coord-MLP, scatters.
// Shared: eW1 (129x64) + aW1 (128x64) weight tiles + per-thread staging rows.
// ---------------------------------------------------------------------------
__global__ __launch_bounds__(256) void edge_kernel(
    const float* __restrict__ nodes, const float* __restrict__ coord,
    const int*   __restrict__ edges,
    const float* __restrict__ eW1, const float* __restrict__ eb1,
    const float* __restrict__ eW2, const float* __restrict__ eb2,
    const float* __restrict__ aW1, const float* __restrict__ ab1,
    const float* __restrict__ aW2, const float* __restrict__ ab2,
    const float* __restrict__ cW1, const float* __restrict__ cb1,
    const float* __restrict__ cW2, const float* __restrict__ cb2,
    float* __restrict__ coord_out, int n_edges) {
    extern __shared__ float sm[];
    float* sE1 = sm;                 // 129*64 = 8256 floats
    float* sA1 = sm + 8256;          // 128*64 = 8192 floats
    float* buf = sm + 8256 + 8192;   // 256*TS floats

    int t = threadIdx.x;
    for (int i = t; i < 129 * 64; i += 256) sE1[i] = eW1[i];
    for (int i = t; i < 128 * 64; i += 256) sA1[i] = aW1[i];
    __syncthreads();

    int e = blockIdx.x * 256 + t;
    if (e >= n_edges) return;

    int r = edges[e];
    int c = edges[n_edges + e];

    float d0 = coord[3*r+0] - coord[3*c+0];
    float d1 = coord[3*r+1] - coord[3*c+1];
    float d2 = coord[3*r+2] - coord[3*c+2];
    float radial = d0*d0 + d1*d1 + d2*d2;

    float u[64], v[64];           // edge-MLP acc / attention acc
    init_from_bias(eb1, u);
    init_from_bias(ab1, v);

    const float4* nod4 = (const float4*)nodes;
    size_t baseR = (size_t)r * 16, baseC = (size_t)c * 16;

    // src features: rows 0..63 of [eW1|aW1]
#pragma unroll 2
    for (int k4 = 0; k4 < 16; k4++) {
        float4 s = __ldg(&nod4[baseR + k4]);
        fma_dual_sh(s.x, sE1 + (4*k4+0)*64, sA1 + (4*k4+0)*64, u, v);
        fma_dual_sh(s.y, sE1 + (4*k4+1)*64, sA1 + (4*k4+1)*64, u, v);
        fma_dual_sh(s.z, sE1 + (4*k4+2)*64, sA1 + (4*k4+2)*64, u, v);
        fma_dual_sh(s.w, sE1 + (4*k4+3)*64, sA1 + (4*k4+3)*64, u, v);
    }
    // tgt features: rows 64..127
#pragma unroll 2
    for (int k4 = 0; k4 < 16; k4++) {
        float4 s = __ldg(&nod4[baseC + k4]);
        fma_dual_sh(s.x, sE1 + (64+4*k4+0)*64, sA1 + (64+4*k4+0)*64, u, v);
        fma_dual_sh(s.y, sE1 + (64+4*k4+1)*64, sA1 + (64+4*k4+1)*64, u, v);
        fma_dual_sh(s.z, sE1 + (64+4*k4+2)*64, sA1 + (64+4*k4+2)*64, u, v);
        fma_dual_sh(s.w, sE1 + (64+4*k4+3)*64, sA1 + (64+4*k4+3)*64, u, v);
    }
    // radial row (edge MLP only): row 128
    {
        const float4* w4 = (const float4*)(sE1 + 128 * 64);
#pragma unroll
        for (int j = 0; j < 16; j++) {
            float4 w = w4[j];
            u[4*j+0] += radial * w.x; u[4*j+1] += radial * w.y;
            u[4*j+2] += radial * w.z; u[4*j+3] += radial * w.w;
        }
    }

    float* my = buf + t * TS;

    // ---- attention: a = sigmoid(tanhshrink(v) . aW2 + ab2) ----
#pragma unroll
    for (int k = 0; k < 64; k++) my[k] = v[k];
    float s_att = __ldg(ab2);
#pragma unroll 1
    for (int k = 0; k < 64; k++) {
        float x = my[k];
        s_att += (x - tanhf(x)) * __ldg(&aW2[k]);
    }
    float a_gate = 1.0f / (1.0f + expf(-s_att));

    // ---- edge MLP layer 2: v = tanhshrink(u) @ eW2 + eb2 ----
#pragma unroll
    for (int k = 0; k < 64; k++) my[k] = u[k];
    init_from_bias(eb2, v);
#pragma unroll 1
    for (int k = 0; k < 64; k++) {
        float x = my[k];
        x = x - tanhf(x);
        fma_one_g(x, eW2 + k * 64, v);
    }

    // ---- gate + coord MLP L1, scatter edge_feat to g_agg[row] ----
#pragma unroll
    for (int k = 0; k < 64; k++) my[k] = v[k];
    init_from_bias(cb1, u);
    float* aggRow = g_agg + (size_t)r * 64;
#pragma unroll 1
    for (int k = 0; k < 64; k++) {
        float x = my[k];
        x = (x - tanhf(x)) * a_gate;     // edge_feat[k]
        atomicAdd(aggRow + k, x);
        fma_one_g(x, cW1 + k * 64, u);
    }

    // ---- coord scalar: sc = tanhshrink(u) . cW2 + cb2 ----
#pragma unroll
    for (int k = 0; k < 64; k++) my[k] = u[k];
    float sc = __ldg(cb2);
#pragma unroll 1
    for (int k = 0; k < 64; k++) {
        float x = my[k];
        sc += (x - tanhf(x)) * __ldg(&cW2[k]);
    }
    atomicAdd(&coord_out[3*r+0], d0 * sc);
    atomicAdd(&coord_out[3*r+1], d1 * sc);
    atomicAdd(&coord_out[3*r+2], d2 * sc);
}

// ---------------------------------------------------------------------------
// Node kernel: out = nodes + tanhshrink([nodes|agg] @ nW1 + nb1) @ nW2 + nb2
// ---------------------------------------------------------------------------
__global__ __launch_bounds__(256) void node_kernel(
    const float* __restrict__ nodes,
    const float* __restrict__ nW1, const float* __restrict__ nb1,
    const float* __restrict__ nW2, const float* __restrict__ nb2,
    float* __restrict__ out, int n) {
    extern __shared__ float sm[];
    float* my = sm + threadIdx.x * TS;
    int i = blockIdx.x * 256 + threadIdx.x;
    if (i >= n) return;

    float u[64];
    init_from_bias(nb1, u);
    const float4* nod4 = (const float4*)nodes;
    const float4* agg4 = (const float4*)g_agg;
    size_t base = (size_t)i * 16;

#pragma unroll 2
    for (int k4 = 0; k4 < 16; k4++) {
        float4 x = __ldg(&nod4[base + k4]);
        fma_one_g(x.x, nW1 + (4*k4+0)*64, u);
        fma_one_g(x.y, nW1 + (4*k4+1)*64, u);
        fma_one_g(x.z, nW1 + (4*k4+2)*64, u);
        fma_one_g(x.w, nW1 + (4*k4+3)*64, u);
    }
#pragma unroll 2
    for (int k4 = 0; k4 < 16; k4++) {
        float4 g = agg4[base + k4];
        fma_one_g(g.x, nW1 + (64+4*k4+0)*64, u);
        fma_one_g(g.y, nW1 + (64+4*k4+1)*64, u);
        fma_one_g(g.z, nW1 + (64+4*k4+2)*64, u);
        fma_one_g(g.w, nW1 + (64+4*k4+3)*64, u);
    }

#pragma unroll
    for (int k = 0; k < 64; k++) my[k] = u[k];
    float v[64];
    init_from_bias(nb2, v);
#pragma unroll 1
    for (int k = 0; k < 64; k++) {
        float x = my[k];
        x = x - tanhf(x);
        fma_one_g(x, nW2 + k * 64, v);
    }

    float4* o4 = (float4*)out;
#pragma unroll
    for (int j = 0; j < 16; j++) {
        float4 nv = __ldg(&nod4[base + j]);
        float4 w;
        w.x = nv.x + v[4*j+0];
        w.y = nv.y + v[4*j+1];
        w.z = nv.z + v[4*j+2];
        w.w = nv.w + v[4*j+3];
        o4[base + j] = w;
    }
}

// ---------------------------------------------------------------------------
extern "C" void kernel_launch(void* const* d_in, const int* in_sizes, int n_in,
                              void* d_out, int out_size) {
    const float* nodes = (const float*)d_in[0];
    const float* coord = (const float*)d_in[1];
    const int*   edges = (const int*)d_in[2];
    const float* eW1 = (const float*)d_in[3];
    const float* eb1 = (const float*)d_in[4];
    const float* eW2 = (const float*)d_in[5];
    const float* eb2 = (const float*)d_in[6];
    const float* aW1 = (const float*)d_in[7];
    const float* ab1 = (const float*)d_in[8];
    const float* aW2 = (const float*)d_in[9];
    const float* ab2 = (const float*)d_in[10];
    const float* nW1 = (const float*)d_in[11];
    const float* nb1 = (const float*)d_in[12];
    const float* nW2 = (const float*)d_in[13];
    const float* nb2 = (const float*)d_in[14];
    const float* cW1 = (const float*)d_in[15];
    const float* cb1 = (const float*)d_in[16];
    const float* cW2 = (const float*)d_in[17];
    const float* cb2 = (const float*)d_in[18];

    int n = in_sizes[0] / NFEAT;            // 50000
    int n_edges = in_sizes[2] / 2;          // 800000

    float* out = (float*)d_out;
    float* nodes_out = out;                  // [n, 64]
    float* coord_out = out + (size_t)n * NFEAT;  // [n, 3]

    const size_t smem_edge = (size_t)(8256 + 8192 + 256 * TS) * sizeof(float);
    const size_t smem_node = (size_t)(256 * TS) * sizeof(float);
    cudaFuncSetAttribute(edge_kernel, cudaFuncAttributeMaxDynamicSharedMemorySize,
                         (int)smem_edge);
    cudaFuncSetAttribute(node_kernel, cudaFuncAttributeMaxDynamicSharedMemorySize,
                         (int)smem_node);

    int init_threads = 256;
    int init_blocks = (n * NFEAT + init_threads - 1) / init_threads;
    init_kernel<<<init_blocks, init_threads>>>(coord, coord_out, n);

    int edge_blocks = (n_edges + 255) / 256;
    edge_kernel<<<edge_blocks, 256, smem_edge>>>(
        nodes, coord, edges,
        eW1, eb1, eW2, eb2,
        aW1, ab1, aW2, ab2,
        cW1, cb1, cW2, cb2,
        coord_out, n_edges);

    int node_blocks = (n + 255) / 256;
    node_kernel<<<node_blocks, 256, smem_node>>>(
        nodes, nW1, nb1, nW2, nb2, nodes_out, n);
}

// round 3
// speedup vs baseline: 2.0509x; 2.0509x over previous
#include <cuda_runtime.h>
#include <math.h>

#define NFEAT 64
#define NNODES 50000
#define TS 65              // staging stride: 65 ≡ 1 (mod 32) -> conflict-free

// Scratch (device globals; no allocation allowed)
__device__ float g_agg[NNODES * NFEAT];          // aggregated edge features
__device__ float g_preR[NNODES * 128];           // [PE_src | PA_src] per node
__device__ float g_preC[NNODES * 128];           // [PE_tgt | PA_tgt] per node

// Branchless tanhshrink: x - tanh(x), computed WITHOUT cancellation.
// |x| < 0.55 : Taylor  x^3*(1/3 - 2/15 x^2 + 17/315 x^4 - 62/2835 x^6 + 1382/155925 x^8)
// |x| >= 0.55: |x| - 1 + 2/(exp(2|x|)+1), sign restored.  MUFU ex2 + rcp.
__device__ __forceinline__ float tshrink(float x) {
    float ax = fabsf(x);
    float x2 = x * x;
    float p = 0.33333333f + x2 * (-0.13333333f + x2 * (0.05396825f
              + x2 * (-0.02186949f + x2 * 0.00886324f)));
    float small = x * x2 * p;
    float e = __expf(2.0f * ax);
    float big = ax - 1.0f + __fdividef(2.0f, e + 1.0f);
    big = copysignf(big, x);
    return ax < 0.55f ? small : big;
}

__device__ __forceinline__ float sigmoidf_fast(float x) {
    return __fdividef(1.0f, 1.0f + __expf(-x));
}

// acc[0..63] += x * w[0..63], weights from GLOBAL (uniform -> L1 broadcast)
__device__ __forceinline__ void fma_one_g(float x, const float* __restrict__ w, float* acc) {
    const float4* w4 = (const float4*)w;
#pragma unroll
    for (int j = 0; j < 16; j++) {
        float4 t = __ldg(&w4[j]);
        acc[4*j+0] += x * t.x; acc[4*j+1] += x * t.y;
        acc[4*j+2] += x * t.z; acc[4*j+3] += x * t.w;
    }
}

// acc[0..63] += x * w[0..63], weights from SHARED
__device__ __forceinline__ void fma_one_sh(float x, const float* w, float* acc) {
    const float4* w4 = (const float4*)w;
#pragma unroll
    for (int j = 0; j < 16; j++) {
        float4 t = w4[j];
        acc[4*j+0] += x * t.x; acc[4*j+1] += x * t.y;
        acc[4*j+2] += x * t.z; acc[4*j+3] += x * t.w;
    }
}

__device__ __forceinline__ void init_from_bias(const float* __restrict__ b, float* acc) {
    const float4* b4 = (const float4*)b;
#pragma unroll
    for (int j = 0; j < 16; j++) {
        float4 t = __ldg(&b4[j]);
        acc[4*j+0] = t.x; acc[4*j+1] = t.y; acc[4*j+2] = t.z; acc[4*j+3] = t.w;
    }
}

// ---------------------------------------------------------------------------
// Init: zero agg buffer, seed coord_out = coord
// ---------------------------------------------------------------------------
__global__ void init_kernel(const float* __restrict__ coord, float* __restrict__ coord_out,
                            int n) {
    int i = blockIdx.x * blockDim.x + threadIdx.x;
    if (i < n * NFEAT) g_agg[i] = 0.0f;
    if (i < n * 3) coord_out[i] = coord[i];
}

// ---------------------------------------------------------------------------
// Precompute: per node, the 4 linear projections used by every incident edge.
//   g_preR[i] = [ nodes[i] @ eW1[0:64]   | nodes[i] @ aW1[0:64]   ]   (src role)
//   g_preC[i] = [ nodes[i] @ eW1[64:128] | nodes[i] @ aW1[64:128] ]   (tgt role)
// Biases NOT included (added once per edge).
// ---------------------------------------------------------------------------
__global__ __launch_bounds__(256) void pre_kernel(
    const float* __restrict__ nodes,
    const float* __restrict__ eW1, const float* __restrict__ aW1, int n) {
    extern __shared__ float sm[];
    float* my = sm + threadIdx.x * TS;
    int i = blockIdx.x * 256 + threadIdx.x;
    if (i >= n) return;

    // stage node row
    const float4* nod4 = (const float4*)nodes;
    size_t base = (size_t)i * 16;
#pragma unroll
    for (int j = 0; j < 16; j++) {
        float4 t = __ldg(&nod4[base + j]);
        my[4*j+0] = t.x; my[4*j+1] = t.y; my[4*j+2] = t.z; my[4*j+3] = t.w;
    }

    float acc[64];
    float4* outR = (float4*)(g_preR + (size_t)i * 128);
    float4* outC = (float4*)(g_preC + (size_t)i * 128);

    // PE_src
#pragma unroll
    for (int j = 0; j < 64; j++) acc[j] = 0.0f;
#pragma unroll 1
    for (int k = 0; k < 64; k++) fma_one_g(my[k], eW1 + k * 64, acc);
#pragma unroll
    for (int j = 0; j < 16; j++) outR[j] = make_float4(acc[4*j], acc[4*j+1], acc[4*j+2], acc[4*j+3]);

    // PA_src
#pragma unroll
    for (int j = 0; j < 64; j++) acc[j] = 0.0f;
#pragma unroll 1
    for (int k = 0; k < 64; k++) fma_one_g(my[k], aW1 + k * 64, acc);
#pragma unroll
    for (int j = 0; j < 16; j++) outR[16+j] = make_float4(acc[4*j], acc[4*j+1], acc[4*j+2], acc[4*j+3]);

    // PE_tgt
#pragma unroll
    for (int j = 0; j < 64; j++) acc[j] = 0.0f;
#pragma unroll 1
    for (int k = 0; k < 64; k++) fma_one_g(my[k], eW1 + (64 + k) * 64, acc);
#pragma unroll
    for (int j = 0; j < 16; j++) outC[j] = make_float4(acc[4*j], acc[4*j+1], acc[4*j+2], acc[4*j+3]);

    // PA_tgt
#pragma unroll
    for (int j = 0; j < 64; j++) acc[j] = 0.0f;
#pragma unroll 1
    for (int k = 0; k < 64; k++) fma_one_g(my[k], aW1 + (64 + k) * 64, acc);
#pragma unroll
    for (int j = 0; j < 16; j++) outC[16+j] = make_float4(acc[4*j], acc[4*j+1], acc[4*j+2], acc[4*j+3]);
}

// ---------------------------------------------------------------------------
// Edge kernel: one thread per edge, using precomputed projections.
// Shared: eW2 (64x64) + cW1 (64x64) + small vectors + per-thread staging rows.
// ---------------------------------------------------------------------------
#define SM_W2   0
#define SM_C1   4096
#define SM_MISC 8192        // eb1[64] w128[64] ab1[64] aW2[64] eb2[64] cb1[64] cW2[64] ab2 cb2
#define SM_BUF  8704

__global__ __launch_bounds__(256) void edge_kernel(
    const float* __restrict__ coord,
    const int*   __restrict__ edges,
    const float* __restrict__ eW1, const float* __restrict__ eb1,
    const float* __restrict__ eW2, const float* __restrict__ eb2,
    const float* __restrict__ ab1,
    const float* __restrict__ aW2, const float* __restrict__ ab2,
    const float* __restrict__ cW1, const float* __restrict__ cb1,
    const float* __restrict__ cW2, const float* __restrict__ cb2,
    float* __restrict__ coord_out, int n_edges) {
    extern __shared__ float sm[];
    int t = threadIdx.x;

    for (int i = t; i < 4096; i += 256) { sm[SM_W2 + i] = eW2[i]; sm[SM_C1 + i] = cW1[i]; }
    if (t < 64) {
        sm[SM_MISC +       t] = eb1[t];
        sm[SM_MISC +  64 + t] = eW1[128 * 64 + t];   // radial row
        sm[SM_MISC + 128 + t] = ab1[t];
        sm[SM_MISC + 192 + t] = aW2[t];
        sm[SM_MISC + 256 + t] = eb2[t];
        sm[SM_MISC + 320 + t] = cb1[t];
        sm[SM_MISC + 384 + t] = cW2[t];
    }
    if (t == 0) { sm[SM_MISC + 448] = ab2[0]; sm[SM_MISC + 449] = cb2[0]; }
    __syncthreads();

    const float* eb1s  = sm + SM_MISC;
    const float* w128s = sm + SM_MISC + 64;
    const float* ab1s  = sm + SM_MISC + 128;
    const float* aW2s  = sm + SM_MISC + 192;
    const float* eb2s  = sm + SM_MISC + 256;
    const float* cb1s  = sm + SM_MISC + 320;
    const float* cW2s  = sm + SM_MISC + 384;
    float* my = sm + SM_BUF + t * TS;

    int e = blockIdx.x * 256 + t;
    if (e >= n_edges) return;

    int r = edges[e];
    int c = edges[n_edges + e];

    float d0 = coord[3*r+0] - coord[3*c+0];
    float d1 = coord[3*r+1] - coord[3*c+1];
    float d2 = coord[3*r+2] - coord[3*c+2];
    float radial = d0*d0 + d1*d1 + d2*d2;

    const float4* pr = (const float4*)(g_preR + (size_t)r * 128);
    const float4* pc = (const float4*)(g_preC + (size_t)c * 128);

    // ---- attention gate: stream over PA halves ----
    float s_att = sm[SM_MISC + 448];
#pragma unroll 4
    for (int j = 0; j < 16; j++) {
        float4 a4 = pr[16 + j];
        float4 b4 = pc[16 + j];
        s_att += tshrink(a4.x + b4.x + ab1s[4*j+0]) * aW2s[4*j+0];
        s_att += tshrink(a4.y + b4.y + ab1s[4*j+1]) * aW2s[4*j+1];
        s_att += tshrink(a4.z + b4.z + ab1s[4*j+2]) * aW2s[4*j+2];
        s_att += tshrink(a4.w + b4.w + ab1s[4*j+3]) * aW2s[4*j+3];
    }
    float gate = sigmoidf_fast(s_att);

    // ---- hidden: stage tanhshrink(u) for edge-MLP L2 ----
#pragma unroll 4
    for (int j = 0; j < 16; j++) {
        float4 a4 = pr[j];
        float4 b4 = pc[j];
        my[4*j+0] = tshrink(a4.x + b4.x + radial * w128s[4*j+0] + eb1s[4*j+0]);
        my[4*j+1] = tshrink(a4.y + b4.y + radial * w128s[4*j+1] + eb1s[4*j+1]);
        my[4*j+2] = tshrink(a4.z + b4.z + radial * w128s[4*j+2] + eb1s[4*j+2]);
        my[4*j+3] = tshrink(a4.w + b4.w + radial * w128s[4*j+3] + eb1s[4*j+3]);
    }

    // ---- edge MLP layer 2 (GEMV, weights from shared) ----
    float acc[64];
#pragma unroll
    for (int j = 0; j < 64; j++) acc[j] = eb2s[j];
#pragma unroll 1
    for (int k = 0; k < 64; k++) fma_one_sh(my[k], sm + SM_W2 + k * 64, acc);

    // ---- gate + scatter edge_feat, stage for coord MLP ----
    float* aggRow = g_agg + (size_t)r * 64;
#pragma unroll
    for (int j = 0; j < 16; j++) {
        float f0 = tshrink(acc[4*j+0]) * gate;
        float f1 = tshrink(acc[4*j+1]) * gate;
        float f2 = tshrink(acc[4*j+2]) * gate;
        float f3 = tshrink(acc[4*j+3]) * gate;
        my[4*j+0] = f0; my[4*j+1] = f1; my[4*j+2] = f2; my[4*j+3] = f3;
        asm volatile("red.global.add.v4.f32 [%0], {%1,%2,%3,%4};"
                     :: "l"(aggRow + 4*j), "f"(f0), "f"(f1), "f"(f2), "f"(f3)
                     : "memory");
    }

    // ---- coord MLP layer 1 (GEMV, weights from shared) ----
#pragma unroll
    for (int j = 0; j < 64; j++) acc[j] = cb1s[j];
#pragma unroll 1
    for (int k = 0; k < 64; k++) fma_one_sh(my[k], sm + SM_C1 + k * 64, acc);

    // ---- coord scalar + scatter ----
    float sc = sm[SM_MISC + 449];
#pragma unroll
    for (int k = 0; k < 64; k++) sc += tshrink(acc[k]) * cW2s[k];

    atomicAdd(&coord_out[3*r+0], d0 * sc);
    atomicAdd(&coord_out[3*r+1], d1 * sc);
    atomicAdd(&coord_out[3*r+2], d2 * sc);
}

// ---------------------------------------------------------------------------
// Node kernel: out = nodes + tanhshrink([nodes|agg] @ nW1 + nb1) @ nW2 + nb2
// ---------------------------------------------------------------------------
__global__ __launch_bounds__(256) void node_kernel(
    const float* __restrict__ nodes,
    const float* __restrict__ nW1, const float* __restrict__ nb1,
    const float* __restrict__ nW2, const float* __restrict__ nb2,
    float* __restrict__ out, int n) {
    extern __shared__ float sm[];
    float* my = sm + threadIdx.x * TS;
    int i = blockIdx.x * 256 + threadIdx.x;
    if (i >= n) return;

    float u[64];
    init_from_bias(nb1, u);
    const float4* nod4 = (const float4*)nodes;
    const float4* agg4 = (const float4*)g_agg;
    size_t base = (size_t)i * 16;

#pragma unroll 2
    for (int k4 = 0; k4 < 16; k4++) {
        float4 x = __ldg(&nod4[base + k4]);
        fma_one_g(x.x, nW1 + (4*k4+0)*64, u);
        fma_one_g(x.y, nW1 + (4*k4+1)*64, u);
        fma_one_g(x.z, nW1 + (4*k4+2)*64, u);
        fma_one_g(x.w, nW1 + (4*k4+3)*64, u);
    }
#pragma unroll 2
    for (int k4 = 0; k4 < 16; k4++) {
        float4 g = agg4[base + k4];
        fma_one_g(g.x, nW1 + (64+4*k4+0)*64, u);
        fma_one_g(g.y, nW1 + (64+4*k4+1)*64, u);
        fma_one_g(g.z, nW1 + (64+4*k4+2)*64, u);
        fma_one_g(g.w, nW1 + (64+4*k4+3)*64, u);
    }

#pragma unroll
    for (int k = 0; k < 64; k++) my[k] = tshrink(u[k]);
    float v[64];
    init_from_bias(nb2, v);
#pragma unroll 1
    for (int k = 0; k < 64; k++) fma_one_g(my[k], nW2 + k * 64, v);

    float4* o4 = (float4*)out;
#pragma unroll
    for (int j = 0; j < 16; j++) {
        float4 nv = __ldg(&nod4[base + j]);
        float4 w;
        w.x = nv.x + v[4*j+0];
        w.y = nv.y + v[4*j+1];
        w.z = nv.z + v[4*j+2];
        w.w = nv.w + v[4*j+3];
        o4[base + j] = w;
    }
}

// ---------------------------------------------------------------------------
extern "C" void kernel_launch(void* const* d_in, const int* in_sizes, int n_in,
                              void* d_out, int out_size) {
    const float* nodes = (const float*)d_in[0];
    const float* coord = (const float*)d_in[1];
    const int*   edges = (const int*)d_in[2];
    const float* eW1 = (const float*)d_in[3];
    const float* eb1 = (const float*)d_in[4];
    const float* eW2 = (const float*)d_in[5];
    const float* eb2 = (const float*)d_in[6];
    const float* aW1 = (const float*)d_in[7];
    const float* ab1 = (const float*)d_in[8];
    const float* aW2 = (const float*)d_in[9];
    const float* ab2 = (const float*)d_in[10];
    const float* nW1 = (const float*)d_in[11];
    const float* nb1 = (const float*)d_in[12];
    const float* nW2 = (const float*)d_in[13];
    const float* nb2 = (const float*)d_in[14];
    const float* cW1 = (const float*)d_in[15];
    const float* cb1 = (const float*)d_in[16];
    const float* cW2 = (const float*)d_in[17];
    const float* cb2 = (const float*)d_in[18];

    int n = in_sizes[0] / NFEAT;            // 50000
    int n_edges = in_sizes[2] / 2;          // 800000

    float* out = (float*)d_out;
    float* nodes_out = out;
    float* coord_out = out + (size_t)n * NFEAT;

    const size_t smem_stage = (size_t)(256 * TS) * sizeof(float);                 // 66.5 KB
    const size_t smem_edge  = (size_t)(8704 + 256 * TS) * sizeof(float);          // ~101 KB
    cudaFuncSetAttribute(pre_kernel,  cudaFuncAttributeMaxDynamicSharedMemorySize, (int)smem_stage);
    cudaFuncSetAttribute(edge_kernel, cudaFuncAttributeMaxDynamicSharedMemorySize, (int)smem_edge);
    cudaFuncSetAttribute(node_kernel, cudaFuncAttributeMaxDynamicSharedMemorySize, (int)smem_stage);

    int init_blocks = (n * NFEAT + 255) / 256;
    init_kernel<<<init_blocks, 256>>>(coord, coord_out, n);

    int pre_blocks = (n + 255) / 256;
    pre_kernel<<<pre_blocks, 256, smem_stage>>>(nodes, eW1, aW1, n);

    int edge_blocks = (n_edges + 255) / 256;
    edge_kernel<<<edge_blocks, 256, smem_edge>>>(
        coord, edges,
        eW1, eb1, eW2, eb2,
        ab1, aW2, ab2,
        cW1, cb1, cW2, cb2,
        coord_out, n_edges);

    node_kernel<<<pre_blocks, 256, smem_stage>>>(
        nodes, nW1, nb1, nW2, nb2, nodes_out, n);
}